// round 1
// baseline (speedup 1.0000x reference)
#include <cuda_runtime.h>
#include <cstdint>

#define FULL_MASK 0xFFFFFFFFu

// ------------------------- device scratch (no allocation allowed) ----------
__device__ float g_WqT[16 * 512];
__device__ float g_WvT[16 * 512];
__device__ float g_partial[8192 * 20];   // per-block partials: 4 denom + 16 num
__device__ float g_U[512 * 4];           // folded attention matrix (incl 1/sqrt(128))
__device__ float g_c[4];                 // folded bias (incl 1/sqrt(128))
__device__ float g_vals[512];            // per-head value vectors (flattened)

// ------------------------- f32x2 helpers -----------------------------------
__device__ __forceinline__ unsigned long long pack2(float lo, float hi) {
    unsigned long long r;
    asm("mov.b64 %0, {%1, %2};" : "=l"(r) : "f"(lo), "f"(hi));
    return r;
}
__device__ __forceinline__ void unpack2(unsigned long long v, float& lo, float& hi) {
    asm("mov.b64 {%0, %1}, %2;" : "=f"(lo), "=f"(hi) : "l"(v));
}
__device__ __forceinline__ void fma2(unsigned long long& acc,
                                     unsigned long long a, unsigned long long b) {
    asm("fma.rn.f32x2 %0, %1, %2, %0;" : "+l"(acc) : "l"(a), "l"(b));
}

__device__ __forceinline__ float silu_fast(float x) {
    return __fdividef(x, 1.0f + __expf(-x));
}

// ------------------------- kernel 0: transpose Wq/Wv (512x16 -> 16x512) ----
__global__ void __launch_bounds__(512) k_transpose(const float* __restrict__ Wq,
                                                   const float* __restrict__ Wv) {
    int t = threadIdx.x;
#pragma unroll
    for (int i = 0; i < 16; i++) {
        g_WqT[i * 512 + t] = Wq[t * 16 + i];
        g_WvT[i * 512 + t] = Wv[t * 16 + i];
    }
}

// ------------------------- kernel 1: register-attention partials -----------
// 16 rows per block (one warp per row). Lane c<16 owns q-component c,
// lane 16+c owns v-component c. Full 512-dot per lane with f32x2.
__global__ void __launch_bounds__(512) k_pass1(const float* __restrict__ h,
                                               const float* __restrict__ rk,
                                               const float* __restrict__ bq,
                                               const float* __restrict__ bv,
                                               int n) {
    __shared__ float spart[16][20];
    const int tid = threadIdx.x, warp = tid >> 5, lane = tid & 31;
    const int row = blockIdx.x * 16 + warp;
    const bool valid = (row < n);

    const float* wt = (lane < 16) ? (g_WqT + lane * 512) : (g_WvT + (lane - 16) * 512);
    float comp = 0.f;
    if (valid) {
        const float* hr = h + (size_t)row * 512;
        unsigned long long acc0 = pack2(0.f, 0.f), acc1 = pack2(0.f, 0.f);
#pragma unroll 8
        for (int k = 0; k < 512; k += 4) {
            ulonglong2 hp = *(const ulonglong2*)(hr + k);
            ulonglong2 wp = *(const ulonglong2*)(wt + k);
            fma2(acc0, hp.x, wp.x);
            fma2(acc1, hp.y, wp.y);
        }
        float a, b, c, d;
        unpack2(acc0, a, b);
        unpack2(acc1, c, d);
        comp = (a + b) + (c + d);
        comp += (lane < 16) ? bq[lane] : bv[lane - 16];
    }

    // logits: lanes 0..15 contribute q_c * rk[c]; 2-step xor reduce within groups of 4
    float contrib = (lane < 16) ? comp * rk[lane] : 0.f;
    contrib += __shfl_xor_sync(FULL_MASK, contrib, 1);
    contrib += __shfl_xor_sync(FULL_MASK, contrib, 2);
    float e = __expf(0.5f * contrib);  // 1/sqrt(REG_DIM)=0.5; no max-sub needed (logit ~N(0,1))
    int src = (lane >= 16) ? ((lane - 16) & ~3) : lane;
    float ev = __shfl_sync(FULL_MASK, e, src);

    if (lane < 16) {
        if ((lane & 3) == 0) spart[warp][lane >> 2] = valid ? e : 0.f;
    } else {
        spart[warp][4 + (lane - 16)] = valid ? ev * comp : 0.f;
    }
    __syncthreads();
    if (warp == 0 && lane < 20) {
        float s = 0.f;
#pragma unroll
        for (int w = 0; w < 16; w++) s += spart[w][lane];
        g_partial[blockIdx.x * 20 + lane] = s;
    }
}

// ------------------------- kernel 2: tiny scalar chain (single block) ------
__global__ void __launch_bounds__(512) k_small(int nb,
        const float* __restrict__ lrs, const float* __restrict__ lrb,
        const float* __restrict__ l1s, const float* __restrict__ l1b,
        const float* __restrict__ W1,  const float* __restrict__ b1,
        const float* __restrict__ W2,  const float* __restrict__ b2,
        const float* __restrict__ W3,  const float* __restrict__ b3,
        const float* __restrict__ Wk,  const float* __restrict__ bk) {
    __shared__ float scomp[20];
    __shared__ float sr16[16];
    __shared__ float sx1[512];
    __shared__ float sx2[512];
    __shared__ float sqk[1024];
    const int tid = threadIdx.x, warp = tid >> 5, lane = tid & 31;

    // deterministic reduction of per-block partials
    for (int c = warp; c < 20; c += 16) {
        float s = 0.f;
        for (int i = lane; i < nb; i += 32) s += g_partial[i * 20 + c];
#pragma unroll
        for (int o = 16; o; o >>= 1) s += __shfl_xor_sync(FULL_MASK, s, o);
        if (lane == 0) scomp[c] = s;
    }
    __syncthreads();

    if (tid == 0) {
        float reg[16];
#pragma unroll
        for (int i = 0; i < 16; i++) reg[i] = scomp[4 + i] / scomp[i >> 2];
#pragma unroll
        for (int pass = 0; pass < 2; pass++) {
            const float* sc = pass ? l1s : lrs;
            const float* bc = pass ? l1b : lrb;
            float m = 0.f;
            for (int i = 0; i < 16; i++) m += reg[i];
            m *= (1.f / 16.f);
            float v = 0.f;
            for (int i = 0; i < 16; i++) { float d = reg[i] - m; v += d * d; }
            v *= (1.f / 16.f);
            float inv = rsqrtf(v + 1e-6f);
            for (int i = 0; i < 16; i++) reg[i] = (reg[i] - m) * inv * sc[i] + bc[i];
        }
        for (int i = 0; i < 16; i++) sr16[i] = reg[i];
    }
    __syncthreads();

    {   // x1 = silu(r16 @ W1 + b1)
        float s = b1[tid];
#pragma unroll
        for (int i = 0; i < 16; i++) s += sr16[i] * W1[i * 512 + tid];
        sx1[tid] = s / (1.f + expf(-s));
    }
    __syncthreads();
    {   // x2 = silu(x1 @ W2 + b2)
        float s = b2[tid];
#pragma unroll 8
        for (int k = 0; k < 512; k++) s += sx1[k] * W2[k * 512 + tid];
        sx2[tid] = s / (1.f + expf(-s));
    }
    __syncthreads();
    {   // qk = x2 @ W3 + b3 (1024 outputs)
        float s0 = b3[tid], s1 = b3[tid + 512];
#pragma unroll 8
        for (int k = 0; k < 512; k++) {
            float x = sx2[k];
            s0 += x * W3[k * 1024 + tid];
            s1 += x * W3[k * 1024 + tid + 512];
        }
        sqk[tid] = s0;
        sqk[tid + 512] = s1;
    }
    __syncthreads();

    {   // fold queries into U = Wk-blocks @ queries (incl 1/sqrt(ATT))
        const float inva = rsqrtf(128.f);
        const float4* wkr = (const float4*)(Wk + (size_t)tid * 512);
        float a[4];
#pragma unroll
        for (int r = 0; r < 4; r++) {
            float s = 0.f;
#pragma unroll
            for (int d4 = 0; d4 < 32; d4++) {
                float4 w = wkr[r * 32 + d4];
                s += w.x * sqk[r * 128 + 4 * d4 + 0];
                s += w.y * sqk[r * 128 + 4 * d4 + 1];
                s += w.z * sqk[r * 128 + 4 * d4 + 2];
                s += w.w * sqk[r * 128 + 4 * d4 + 3];
            }
            a[r] = s * inva;
        }
        ((float4*)g_U)[tid] = make_float4(a[0], a[1], a[2], a[3]);
    }
    g_vals[tid] = sqk[512 + tid];
    if (tid < 4) {
        float s = 0.f;
        for (int d = 0; d < 128; d++) s += bk[tid * 128 + d] * sqk[tid * 128 + d];
        g_c[tid] = s * rsqrtf(128.f);
    }
}

// ------------------------- kernel 3: main per-row pipeline + h2@Wm ---------
// 32 rows/block, 512 threads. Phase A: head softmax + residual + LN2 into
// transposed smem (stride 36). Phase B: f32x2 register-tiled GEMM (8x4/thread),
// silu, residual, LN3, write.
__global__ void __launch_bounds__(512) k_main(const float* __restrict__ h,
        const float* __restrict__ ln2s, const float* __restrict__ ln2b,
        const float* __restrict__ Wm,   const float* __restrict__ bm,
        const float* __restrict__ ln3s, const float* __restrict__ ln3b,
        float* __restrict__ out, int n) {
    extern __shared__ float sm[];
    float* h2t   = sm;                 // [512][36] (col-major, padded)
    float* red   = sm + 512 * 36;      // [2][32][128]
    float* stats = red + 2 * 32 * 128; // [32][2]

    const int tid = threadIdx.x, warp = tid >> 5, lane = tid & 31;
    const int row0 = blockIdx.x * 32;

    float c0 = g_c[0], c1 = g_c[1], c2 = g_c[2], c3 = g_c[3];

    // ---------- Phase A: warp handles rows (2*warp, 2*warp+1) ----------
#pragma unroll
    for (int rr = 0; rr < 2; rr++) {
        const int rloc = warp * 2 + rr;
        const int row = row0 + rloc;
        const bool valid = (row < n);
        const float* hr = h + (size_t)row * 512;

        float l0 = 0.f, l1 = 0.f, l2 = 0.f, l3 = 0.f;
        if (valid) {
#pragma unroll
            for (int t = 0; t < 16; t++) {
                int k = lane + 32 * t;
                float hk = __ldg(hr + k);
                float4 u = __ldg((const float4*)g_U + k);
                l0 += hk * u.x; l1 += hk * u.y; l2 += hk * u.z; l3 += hk * u.w;
            }
        }
#pragma unroll
        for (int o = 16; o; o >>= 1) {
            l0 += __shfl_xor_sync(FULL_MASK, l0, o);
            l1 += __shfl_xor_sync(FULL_MASK, l1, o);
            l2 += __shfl_xor_sync(FULL_MASK, l2, o);
            l3 += __shfl_xor_sync(FULL_MASK, l3, o);
        }
        l0 += c0; l1 += c1; l2 += c2; l3 += c3;
        float mx = fmaxf(fmaxf(l0, l1), fmaxf(l2, l3));
        float e0 = __expf(l0 - mx), e1 = __expf(l1 - mx);
        float e2 = __expf(l2 - mx), e3 = __expf(l3 - mx);
        float sinv = __fdividef(1.f, e0 + e1 + e2 + e3);
        float a0 = e0 * sinv, a1 = e1 * sinv, a2 = e2 * sinv, a3 = e3 * sinv;

        float sum = 0.f, sq = 0.f;
#pragma unroll
        for (int t = 0; t < 16; t++) {
            int k = lane + 32 * t;
            float ar = (t < 4) ? a0 : (t < 8) ? a1 : (t < 12) ? a2 : a3;
            float o_ = valid ? (__ldg(hr + k) + ar * g_vals[k]) : 0.f;
            h2t[k * 36 + rloc] = o_;
            sum += o_; sq += o_ * o_;
        }
#pragma unroll
        for (int o = 16; o; o >>= 1) {
            sum += __shfl_xor_sync(FULL_MASK, sum, o);
            sq  += __shfl_xor_sync(FULL_MASK, sq, o);
        }
        float mean = sum * (1.f / 512.f);
        float var = sq * (1.f / 512.f) - mean * mean;
        float inv = rsqrtf(var + 1e-6f);
#pragma unroll
        for (int t = 0; t < 16; t++) {
            int k = lane + 32 * t;
            float o_ = h2t[k * 36 + rloc];
            h2t[k * 36 + rloc] = (o_ - mean) * inv * __ldg(ln2s + k) + __ldg(ln2b + k);
        }
    }
    __syncthreads();

    // ---------- Phase B: mlp = h2n @ Wm ; thread tile 8 rows x 4 cols ----------
    const int cg = tid & 127;   // column group: cols 4*cg .. 4*cg+3
    const int rg = tid >> 7;    // row group:    rows 8*rg .. 8*rg+7
    unsigned long long acc[4][4];
#pragma unroll
    for (int p = 0; p < 4; p++)
#pragma unroll
        for (int c = 0; c < 4; c++) acc[p][c] = pack2(0.f, 0.f);

    const float4* wm4 = (const float4*)Wm + cg;
    const float* hb0 = h2t + rg * 8;
#pragma unroll 2
    for (int k = 0; k < 512; k++) {
        float4 w = __ldg(wm4 + k * 128);
        unsigned long long w0 = pack2(w.x, w.x), w1 = pack2(w.y, w.y);
        unsigned long long w2 = pack2(w.z, w.z), w3 = pack2(w.w, w.w);
        const float* hb = hb0 + k * 36;
        ulonglong2 ha = *(const ulonglong2*)hb;         // rows 0..3 (pairs 0,1)
        ulonglong2 hc = *(const ulonglong2*)(hb + 4);   // rows 4..7 (pairs 2,3)
        fma2(acc[0][0], ha.x, w0); fma2(acc[0][1], ha.x, w1);
        fma2(acc[0][2], ha.x, w2); fma2(acc[0][3], ha.x, w3);
        fma2(acc[1][0], ha.y, w0); fma2(acc[1][1], ha.y, w1);
        fma2(acc[1][2], ha.y, w2); fma2(acc[1][3], ha.y, w3);
        fma2(acc[2][0], hc.x, w0); fma2(acc[2][1], hc.x, w1);
        fma2(acc[2][2], hc.x, w2); fma2(acc[2][3], hc.x, w3);
        fma2(acc[3][0], hc.y, w0); fma2(acc[3][1], hc.y, w1);
        fma2(acc[3][2], hc.y, w2); fma2(acc[3][3], hc.y, w3);
    }

    // epilogue: + bm, silu, + h2n residual
    float4 bmv = __ldg((const float4*)bm + cg);
    float bmf[4] = {bmv.x, bmv.y, bmv.z, bmv.w};
    float y[8][4];
#pragma unroll
    for (int p = 0; p < 4; p++)
#pragma unroll
        for (int c = 0; c < 4; c++) {
            float lo, hi;
            unpack2(acc[p][c], lo, hi);
            y[2 * p + 0][c] = lo + bmf[c];
            y[2 * p + 1][c] = hi + bmf[c];
        }
#pragma unroll
    for (int c = 0; c < 4; c++) {
        int col = cg * 4 + c;
#pragma unroll
        for (int r = 0; r < 8; r++) {
            float h2v = h2t[col * 36 + rg * 8 + r];
            y[r][c] = h2v + silu_fast(y[r][c]);
        }
    }

    // LN3 row stats
#pragma unroll
    for (int r = 0; r < 8; r++) {
        int rl = rg * 8 + r;
        float ps  = y[r][0] + y[r][1] + y[r][2] + y[r][3];
        float pss = y[r][0] * y[r][0] + y[r][1] * y[r][1] +
                    y[r][2] * y[r][2] + y[r][3] * y[r][3];
        red[rl * 128 + cg] = ps;
        red[4096 + rl * 128 + cg] = pss;
    }
    __syncthreads();
#pragma unroll
    for (int rr = 0; rr < 2; rr++) {
        int rl = warp * 2 + rr;
        float s  = red[rl * 128 + lane]        + red[rl * 128 + lane + 32] +
                   red[rl * 128 + lane + 64]   + red[rl * 128 + lane + 96];
        float sq = red[4096 + rl * 128 + lane]      + red[4096 + rl * 128 + lane + 32] +
                   red[4096 + rl * 128 + lane + 64] + red[4096 + rl * 128 + lane + 96];
#pragma unroll
        for (int o = 16; o; o >>= 1) {
            s  += __shfl_xor_sync(FULL_MASK, s, o);
            sq += __shfl_xor_sync(FULL_MASK, sq, o);
        }
        if (lane == 0) {
            float mean = s * (1.f / 512.f);
            float var = sq * (1.f / 512.f) - mean * mean;
            stats[rl * 2 + 0] = mean;
            stats[rl * 2 + 1] = rsqrtf(var + 1e-6f);
        }
    }
    __syncthreads();

    float4 s4 = __ldg((const float4*)ln3s + cg);
    float4 b4 = __ldg((const float4*)ln3b + cg);
#pragma unroll
    for (int r = 0; r < 8; r++) {
        int rl = rg * 8 + r;
        int row = row0 + rl;
        if (row >= n) continue;
        float mean = stats[rl * 2 + 0], inv = stats[rl * 2 + 1];
        float4 o;
        o.x = (y[r][0] - mean) * inv * s4.x + b4.x;
        o.y = (y[r][1] - mean) * inv * s4.y + b4.y;
        o.z = (y[r][2] - mean) * inv * s4.z + b4.z;
        o.w = (y[r][3] - mean) * inv * s4.w + b4.w;
        *(float4*)(out + (size_t)row * 512 + cg * 4) = o;
    }
}

// ------------------------- host launch --------------------------------------
extern "C" void kernel_launch(void* const* d_in, const int* in_sizes, int n_in,
                              void* d_out, int out_size) {
    const float* h    = (const float*)d_in[0];
    // d_in[1] = spin (unused by reference)
    const float* rk   = (const float*)d_in[2];
    const float* Wq   = (const float*)d_in[3];
    const float* bq   = (const float*)d_in[4];
    const float* Wv   = (const float*)d_in[5];
    const float* bv   = (const float*)d_in[6];
    const float* lrs  = (const float*)d_in[7];
    const float* lrb  = (const float*)d_in[8];
    const float* l1s  = (const float*)d_in[9];
    const float* l1b  = (const float*)d_in[10];
    const float* W1   = (const float*)d_in[11];
    const float* b1   = (const float*)d_in[12];
    const float* W2   = (const float*)d_in[13];
    const float* b2   = (const float*)d_in[14];
    const float* W3   = (const float*)d_in[15];
    const float* b3   = (const float*)d_in[16];
    const float* Wk   = (const float*)d_in[17];
    const float* bk   = (const float*)d_in[18];
    const float* ln2s = (const float*)d_in[19];
    const float* ln2b = (const float*)d_in[20];
    const float* Wm   = (const float*)d_in[21];
    const float* bm   = (const float*)d_in[22];
    const float* ln3s = (const float*)d_in[23];
    const float* ln3b = (const float*)d_in[24];
    float* out = (float*)d_out;

    const int n = in_sizes[0] / 512;
    const int nb1 = (n + 15) / 16;
    const int nb3 = (n + 31) / 32;

    const int smem_bytes = (512 * 36 + 2 * 32 * 128 + 64) * (int)sizeof(float);
    cudaFuncSetAttribute(k_main, cudaFuncAttributeMaxDynamicSharedMemorySize, smem_bytes);

    k_transpose<<<1, 512>>>(Wq, Wv);
    k_pass1<<<nb1, 512>>>(h, rk, bq, bv, n);
    k_small<<<1, 512>>>(nb1, lrs, lrb, l1s, l1b, W1, b1, W2, b2, W3, b3, Wk, bk);
    k_main<<<nb3, 512, smem_bytes>>>(h, ln2s, ln2b, Wm, bm, ln3s, ln3b, out, n);
}

// round 2
// speedup vs baseline: 1.8421x; 1.8421x over previous
#include <cuda_runtime.h>
#include <cstdint>

#define FULL_MASK 0xFFFFFFFFu

// ------------------------- device scratch (no allocation allowed) ----------
__device__ float g_u[512 * 4];            // folded logit matrix (Wq @ rk per head)
__device__ float g_c1[4];                 // folded logit bias
__device__ float g_e[131072 * 4];         // per-row softmax numerators
__device__ float g_dpart[8192 * 4];       // per-block denominators (stage 1)
__device__ float g_spart[512 * 4 * 512];  // per-chunk S_r partials (stage 2)
__device__ float g_U[512 * 4];            // folded head-attention matrix (incl 1/sqrt(128))
__device__ float g_c[4];                  // folded head-attention bias
__device__ float g_vals[512];             // per-head value vectors (flattened)

// ------------------------- f32x2 helpers -----------------------------------
__device__ __forceinline__ unsigned long long pack2(float lo, float hi) {
    unsigned long long r;
    asm("mov.b64 %0, {%1, %2};" : "=l"(r) : "f"(lo), "f"(hi));
    return r;
}
__device__ __forceinline__ void unpack2(unsigned long long v, float& lo, float& hi) {
    asm("mov.b64 {%0, %1}, %2;" : "=f"(lo), "=f"(hi) : "l"(v));
}
__device__ __forceinline__ void fma2(unsigned long long& acc,
                                     unsigned long long a, unsigned long long b) {
    asm("fma.rn.f32x2 %0, %1, %2, %0;" : "+l"(acc) : "l"(a), "l"(b));
}
__device__ __forceinline__ float silu_fast(float x) {
    return __fdividef(x, 1.0f + __expf(-x));
}

// ------------------------- kernel: prep (fold Wq/rk -> u, c1) ---------------
__global__ void __launch_bounds__(512) k_prep(const float* __restrict__ Wq,
                                              const float* __restrict__ bq,
                                              const float* __restrict__ rk) {
    int k = threadIdx.x;
    float u[4];
#pragma unroll
    for (int r = 0; r < 4; r++) {
        float s = 0.f;
#pragma unroll
        for (int d = 0; d < 4; d++) s += Wq[k * 16 + 4 * r + d] * rk[4 * r + d];
        u[r] = s;
    }
    ((float4*)g_u)[k] = make_float4(u[0], u[1], u[2], u[3]);
    if (k < 4) {
        float s = 0.f;
#pragma unroll
        for (int d = 0; d < 4; d++) s += bq[4 * k + d] * rk[4 * k + d];
        g_c1[k] = s;
    }
}

// ------------------------- kernel: stage 1 — logits + e + D partials --------
// warp per row, 16 rows/block
__global__ void __launch_bounds__(512) k_logits(const float* __restrict__ h, int n) {
    __shared__ float sD[16][4];
    const int tid = threadIdx.x, warp = tid >> 5, lane = tid & 31;
    const int row = blockIdx.x * 16 + warp;
    const bool valid = (row < n);

    float l0 = 0.f, l1 = 0.f, l2 = 0.f, l3 = 0.f;
    if (valid) {
        const float* hr = h + (size_t)row * 512;
#pragma unroll
        for (int t = 0; t < 16; t++) {
            int k = lane + 32 * t;
            float hk = __ldg(hr + k);
            float4 u = __ldg((const float4*)g_u + k);
            l0 += hk * u.x; l1 += hk * u.y; l2 += hk * u.z; l3 += hk * u.w;
        }
    }
#pragma unroll
    for (int o = 16; o; o >>= 1) {
        l0 += __shfl_xor_sync(FULL_MASK, l0, o);
        l1 += __shfl_xor_sync(FULL_MASK, l1, o);
        l2 += __shfl_xor_sync(FULL_MASK, l2, o);
        l3 += __shfl_xor_sync(FULL_MASK, l3, o);
    }
    float e0 = __expf(0.5f * (l0 + g_c1[0]));
    float e1 = __expf(0.5f * (l1 + g_c1[1]));
    float e2 = __expf(0.5f * (l2 + g_c1[2]));
    float e3 = __expf(0.5f * (l3 + g_c1[3]));
    if (lane == 0) {
        if (valid) ((float4*)g_e)[row] = make_float4(e0, e1, e2, e3);
        float m = valid ? 1.f : 0.f;
        sD[warp][0] = e0 * m; sD[warp][1] = e1 * m;
        sD[warp][2] = e2 * m; sD[warp][3] = e3 * m;
    }
    __syncthreads();
    if (warp == 0 && lane < 4) {
        float s = 0.f;
#pragma unroll
        for (int w = 0; w < 16; w++) s += sD[w][lane];
        g_dpart[blockIdx.x * 4 + lane] = s;
    }
}

// ------------------------- kernel: stage 2 — S_r = e^T @ h ------------------
// block handles 256 rows, thread owns one column
__global__ void __launch_bounds__(512) k_ssum(const float* __restrict__ h, int n) {
    const int c = threadIdx.x;
    const int base = blockIdx.x * 256;
    int lim = n - base; if (lim > 256) lim = 256;
    unsigned long long a01 = pack2(0.f, 0.f), a23 = pack2(0.f, 0.f);
    for (int i = 0; i < lim; i++) {
        const int row = base + i;
        float4 e = __ldg((const float4*)g_e + row);
        float hv = __ldg(h + (size_t)row * 512 + c);
        unsigned long long hd = pack2(hv, hv);
        fma2(a01, hd, pack2(e.x, e.y));
        fma2(a23, hd, pack2(e.z, e.w));
    }
    float s0, s1, s2, s3;
    unpack2(a01, s0, s1);
    unpack2(a23, s2, s3);
    float* dst = g_spart + (size_t)blockIdx.x * 2048;
    dst[0 * 512 + c] = s0;
    dst[1 * 512 + c] = s1;
    dst[2 * 512 + c] = s2;
    dst[3 * 512 + c] = s3;
}

// ------------------------- kernel: tiny scalar chain (single block) ---------
__global__ void __launch_bounds__(512) k_small(int nb1, int nb2,
        const float* __restrict__ Wv,  const float* __restrict__ bv,
        const float* __restrict__ lrs, const float* __restrict__ lrb,
        const float* __restrict__ l1s, const float* __restrict__ l1b,
        const float* __restrict__ W1,  const float* __restrict__ b1,
        const float* __restrict__ W2,  const float* __restrict__ b2,
        const float* __restrict__ W3,  const float* __restrict__ b3,
        const float* __restrict__ Wk,  const float* __restrict__ bk) {
    __shared__ float sS[4 * 512];
    __shared__ float sDv[4];
    __shared__ float sNum[16];
    __shared__ float sr16[16];
    __shared__ float sx1[512];
    __shared__ float sx2[512];
    __shared__ float sqk[1024];
    const int tid = threadIdx.x, warp = tid >> 5, lane = tid & 31;

    // D_r: warps 0..3
    if (warp < 4) {
        float s = 0.f;
        for (int i = lane; i < nb1; i += 32) s += g_dpart[i * 4 + warp];
#pragma unroll
        for (int o = 16; o; o >>= 1) s += __shfl_xor_sync(FULL_MASK, s, o);
        if (lane == 0) sDv[warp] = s;
    }
    // S_r[c]: each thread one column, 4 accumulators
    {
        float s0 = 0.f, s1 = 0.f, s2 = 0.f, s3 = 0.f;
        for (int b = 0; b < nb2; b++) {
            const float* src = g_spart + (size_t)b * 2048;
            s0 += src[0 * 512 + tid];
            s1 += src[1 * 512 + tid];
            s2 += src[2 * 512 + tid];
            s3 += src[3 * 512 + tid];
        }
        sS[0 * 512 + tid] = s0;
        sS[1 * 512 + tid] = s1;
        sS[2 * 512 + tid] = s2;
        sS[3 * 512 + tid] = s3;
    }
    __syncthreads();

    // num[i] = S_{i>>2} . Wv[:, i]  (16 dots, warp each)
    if (warp < 16) {
        const int r = warp >> 2;
        float s = 0.f;
        for (int c = lane; c < 512; c += 32) s += sS[r * 512 + c] * Wv[c * 16 + warp];
#pragma unroll
        for (int o = 16; o; o >>= 1) s += __shfl_xor_sync(FULL_MASK, s, o);
        if (lane == 0) sNum[warp] = s;
    }
    __syncthreads();

    if (tid == 0) {
        float reg[16];
#pragma unroll
        for (int i = 0; i < 16; i++) reg[i] = sNum[i] / sDv[i >> 2] + bv[i];
#pragma unroll
        for (int pass = 0; pass < 2; pass++) {
            const float* sc = pass ? l1s : lrs;
            const float* bc = pass ? l1b : lrb;
            float m = 0.f;
            for (int i = 0; i < 16; i++) m += reg[i];
            m *= (1.f / 16.f);
            float v = 0.f;
            for (int i = 0; i < 16; i++) { float d = reg[i] - m; v += d * d; }
            v *= (1.f / 16.f);
            float inv = rsqrtf(v + 1e-6f);
            for (int i = 0; i < 16; i++) reg[i] = (reg[i] - m) * inv * sc[i] + bc[i];
        }
        for (int i = 0; i < 16; i++) sr16[i] = reg[i];
    }
    __syncthreads();

    {   // x1 = silu(r16 @ W1 + b1)
        float s = b1[tid];
#pragma unroll
        for (int i = 0; i < 16; i++) s += sr16[i] * W1[i * 512 + tid];
        sx1[tid] = s / (1.f + expf(-s));
    }
    __syncthreads();
    {   // x2 = silu(x1 @ W2 + b2)
        float s = b2[tid];
#pragma unroll 8
        for (int k = 0; k < 512; k++) s += sx1[k] * W2[k * 512 + tid];
        sx2[tid] = s / (1.f + expf(-s));
    }
    __syncthreads();
    {   // qk = x2 @ W3 + b3 (1024 outputs)
        float s0 = b3[tid], s1 = b3[tid + 512];
#pragma unroll 8
        for (int k = 0; k < 512; k++) {
            float x = sx2[k];
            s0 += x * W3[k * 1024 + tid];
            s1 += x * W3[k * 1024 + tid + 512];
        }
        sqk[tid] = s0;
        sqk[tid + 512] = s1;
    }
    __syncthreads();

    {   // fold queries into U = Wk-blocks @ queries (incl 1/sqrt(ATT))
        const float inva = rsqrtf(128.f);
        const float4* wkr = (const float4*)(Wk + (size_t)tid * 512);
        float a[4];
#pragma unroll
        for (int r = 0; r < 4; r++) {
            float s = 0.f;
#pragma unroll
            for (int d4 = 0; d4 < 32; d4++) {
                float4 w = wkr[r * 32 + d4];
                s += w.x * sqk[r * 128 + 4 * d4 + 0];
                s += w.y * sqk[r * 128 + 4 * d4 + 1];
                s += w.z * sqk[r * 128 + 4 * d4 + 2];
                s += w.w * sqk[r * 128 + 4 * d4 + 3];
            }
            a[r] = s * inva;
        }
        ((float4*)g_U)[tid] = make_float4(a[0], a[1], a[2], a[3]);
    }
    g_vals[tid] = sqk[512 + tid];
    if (tid < 4) {
        float s = 0.f;
        for (int d = 0; d < 128; d++) s += bk[tid * 128 + d] * sqk[tid * 128 + d];
        g_c[tid] = s * rsqrtf(128.f);
    }
}

// ------------------------- kernel: main per-row pipeline + h2@Wm ------------
// 64 rows/block, 512 threads. Phase A: head softmax + residual + LN2 into
// transposed smem (stride 68). Phase B: f32x2 8x8 register tile GEMM,
// silu, residual, LN3, write.
#define H2STRIDE 68
__global__ void __launch_bounds__(512, 1) k_main(const float* __restrict__ h,
        const float* __restrict__ ln2s, const float* __restrict__ ln2b,
        const float* __restrict__ Wm,   const float* __restrict__ bm,
        const float* __restrict__ ln3s, const float* __restrict__ ln3b,
        float* __restrict__ out, int n) {
    extern __shared__ float sm[];
    float* h2t   = sm;                       // [512][68]
    float* red   = sm + 512 * H2STRIDE;      // [64][64] sums
    float* red2  = red + 64 * 64;            // [64][64] sumsq
    float* stats = red2 + 64 * 64;           // [64][2]

    const int tid = threadIdx.x, warp = tid >> 5, lane = tid & 31;
    const int row0 = blockIdx.x * 64;

    const float c0 = g_c[0], c1 = g_c[1], c2 = g_c[2], c3 = g_c[3];

    // ---------- Phase A: warp handles rows 4*warp .. 4*warp+3 ----------
#pragma unroll
    for (int rr = 0; rr < 4; rr++) {
        const int rloc = warp * 4 + rr;
        const int row = row0 + rloc;
        const bool valid = (row < n);
        const float* hr = h + (size_t)row * 512;

        float l0 = 0.f, l1 = 0.f, l2 = 0.f, l3 = 0.f;
        if (valid) {
#pragma unroll
            for (int t = 0; t < 16; t++) {
                int k = lane + 32 * t;
                float hk = __ldg(hr + k);
                float4 u = __ldg((const float4*)g_U + k);
                l0 += hk * u.x; l1 += hk * u.y; l2 += hk * u.z; l3 += hk * u.w;
            }
        }
#pragma unroll
        for (int o = 16; o; o >>= 1) {
            l0 += __shfl_xor_sync(FULL_MASK, l0, o);
            l1 += __shfl_xor_sync(FULL_MASK, l1, o);
            l2 += __shfl_xor_sync(FULL_MASK, l2, o);
            l3 += __shfl_xor_sync(FULL_MASK, l3, o);
        }
        l0 += c0; l1 += c1; l2 += c2; l3 += c3;
        float mx = fmaxf(fmaxf(l0, l1), fmaxf(l2, l3));
        float e0 = __expf(l0 - mx), e1 = __expf(l1 - mx);
        float e2 = __expf(l2 - mx), e3 = __expf(l3 - mx);
        float sinv = __fdividef(1.f, e0 + e1 + e2 + e3);
        float a0 = e0 * sinv, a1 = e1 * sinv, a2 = e2 * sinv, a3 = e3 * sinv;

        float o_[16];
        float sum = 0.f, sq = 0.f;
#pragma unroll
        for (int t = 0; t < 16; t++) {
            int k = lane + 32 * t;
            float ar = (t < 4) ? a0 : (t < 8) ? a1 : (t < 12) ? a2 : a3;
            float v = valid ? (__ldg(hr + k) + ar * g_vals[k]) : 0.f;
            o_[t] = v;
            sum += v; sq += v * v;
        }
#pragma unroll
        for (int o = 16; o; o >>= 1) {
            sum += __shfl_xor_sync(FULL_MASK, sum, o);
            sq  += __shfl_xor_sync(FULL_MASK, sq, o);
        }
        float mean = sum * (1.f / 512.f);
        float var = sq * (1.f / 512.f) - mean * mean;
        float inv = rsqrtf(var + 1e-6f);
#pragma unroll
        for (int t = 0; t < 16; t++) {
            int k = lane + 32 * t;
            h2t[k * H2STRIDE + rloc] =
                (o_[t] - mean) * inv * __ldg(ln2s + k) + __ldg(ln2b + k);
        }
    }
    __syncthreads();

    // ---------- Phase B: 8 rows x 8 cols per thread ----------
    const int cg = tid & 63;    // column group: cols 4*cg..+3 and 256+4*cg..+3
    const int rg = tid >> 6;    // row group: rows 8*rg..8*rg+7
    unsigned long long acc[4][8];
#pragma unroll
    for (int p = 0; p < 4; p++)
#pragma unroll
        for (int c = 0; c < 8; c++) acc[p][c] = pack2(0.f, 0.f);

    const float4* w0 = (const float4*)Wm + cg;
    const float4* w1 = w0 + 64;
    const float* hb0 = h2t + rg * 8;
#pragma unroll 2
    for (int k = 0; k < 512; k++) {
        float4 wa = __ldg(w0 + k * 128);
        float4 wb = __ldg(w1 + k * 128);
        unsigned long long wd[8];
        wd[0] = pack2(wa.x, wa.x); wd[1] = pack2(wa.y, wa.y);
        wd[2] = pack2(wa.z, wa.z); wd[3] = pack2(wa.w, wa.w);
        wd[4] = pack2(wb.x, wb.x); wd[5] = pack2(wb.y, wb.y);
        wd[6] = pack2(wb.z, wb.z); wd[7] = pack2(wb.w, wb.w);
        const float* hb = hb0 + k * H2STRIDE;
        ulonglong2 hA = *(const ulonglong2*)hb;
        ulonglong2 hB = *(const ulonglong2*)(hb + 4);
        unsigned long long hp[4] = {hA.x, hA.y, hB.x, hB.y};
#pragma unroll
        for (int p = 0; p < 4; p++)
#pragma unroll
            for (int c = 0; c < 8; c++) fma2(acc[p][c], hp[p], wd[c]);
    }

    // epilogue: + bm, silu, + residual
    float4 bma = __ldg((const float4*)bm + cg);
    float4 bmb = __ldg((const float4*)bm + cg + 64);
    float bmf[8] = {bma.x, bma.y, bma.z, bma.w, bmb.x, bmb.y, bmb.z, bmb.w};
    float y[8][8];
#pragma unroll
    for (int p = 0; p < 4; p++)
#pragma unroll
        for (int c = 0; c < 8; c++) {
            float lo, hi;
            unpack2(acc[p][c], lo, hi);
            y[2 * p + 0][c] = lo + bmf[c];
            y[2 * p + 1][c] = hi + bmf[c];
        }
#pragma unroll
    for (int c = 0; c < 8; c++) {
        int col = (c < 4) ? (cg * 4 + c) : (256 + cg * 4 + (c - 4));
#pragma unroll
        for (int r = 0; r < 8; r++) {
            float h2v = h2t[col * H2STRIDE + rg * 8 + r];
            y[r][c] = h2v + silu_fast(y[r][c]);
        }
    }

    // LN3 row partials
#pragma unroll
    for (int r = 0; r < 8; r++) {
        int rl = rg * 8 + r;
        float ps = 0.f, pss = 0.f;
#pragma unroll
        for (int c = 0; c < 8; c++) { ps += y[r][c]; pss += y[r][c] * y[r][c]; }
        red[rl * 64 + cg] = ps;
        red2[rl * 64 + cg] = pss;
    }
    __syncthreads();
#pragma unroll
    for (int rr = 0; rr < 2; rr++) {
        int rl = warp * 2 + rr;  // warps 0..31? only 16 warps -> rows 0..31... fix below
        (void)rl;
    }
    // stats: 16 warps, each handles 4 rows
#pragma unroll
    for (int rr = 0; rr < 4; rr++) {
        int rl = warp * 4 + rr;
        float s  = red[rl * 64 + lane]  + red[rl * 64 + lane + 32];
        float sq = red2[rl * 64 + lane] + red2[rl * 64 + lane + 32];
#pragma unroll
        for (int o = 16; o; o >>= 1) {
            s  += __shfl_xor_sync(FULL_MASK, s, o);
            sq += __shfl_xor_sync(FULL_MASK, sq, o);
        }
        if (lane == 0) {
            float mean = s * (1.f / 512.f);
            float var = sq * (1.f / 512.f) - mean * mean;
            stats[rl * 2 + 0] = mean;
            stats[rl * 2 + 1] = rsqrtf(var + 1e-6f);
        }
    }
    __syncthreads();

    float4 s4a = __ldg((const float4*)ln3s + cg);
    float4 b4a = __ldg((const float4*)ln3b + cg);
    float4 s4b = __ldg((const float4*)ln3s + cg + 64);
    float4 b4b = __ldg((const float4*)ln3b + cg + 64);
#pragma unroll
    for (int r = 0; r < 8; r++) {
        int rl = rg * 8 + r;
        int row = row0 + rl;
        if (row >= n) continue;
        float mean = stats[rl * 2 + 0], inv = stats[rl * 2 + 1];
        float4 o1, o2;
        o1.x = (y[r][0] - mean) * inv * s4a.x + b4a.x;
        o1.y = (y[r][1] - mean) * inv * s4a.y + b4a.y;
        o1.z = (y[r][2] - mean) * inv * s4a.z + b4a.z;
        o1.w = (y[r][3] - mean) * inv * s4a.w + b4a.w;
        o2.x = (y[r][4] - mean) * inv * s4b.x + b4b.x;
        o2.y = (y[r][5] - mean) * inv * s4b.y + b4b.y;
        o2.z = (y[r][6] - mean) * inv * s4b.z + b4b.z;
        o2.w = (y[r][7] - mean) * inv * s4b.w + b4b.w;
        *(float4*)(out + (size_t)row * 512 + cg * 4) = o1;
        *(float4*)(out + (size_t)row * 512 + 256 + cg * 4) = o2;
    }
}

// ------------------------- host launch --------------------------------------
extern "C" void kernel_launch(void* const* d_in, const int* in_sizes, int n_in,
                              void* d_out, int out_size) {
    const float* h    = (const float*)d_in[0];
    const float* rk   = (const float*)d_in[2];
    const float* Wq   = (const float*)d_in[3];
    const float* bq   = (const float*)d_in[4];
    const float* Wv   = (const float*)d_in[5];
    const float* bv   = (const float*)d_in[6];
    const float* lrs  = (const float*)d_in[7];
    const float* lrb  = (const float*)d_in[8];
    const float* l1s  = (const float*)d_in[9];
    const float* l1b  = (const float*)d_in[10];
    const float* W1   = (const float*)d_in[11];
    const float* b1   = (const float*)d_in[12];
    const float* W2   = (const float*)d_in[13];
    const float* b2   = (const float*)d_in[14];
    const float* W3   = (const float*)d_in[15];
    const float* b3   = (const float*)d_in[16];
    const float* Wk   = (const float*)d_in[17];
    const float* bk   = (const float*)d_in[18];
    const float* ln2s = (const float*)d_in[19];
    const float* ln2b = (const float*)d_in[20];
    const float* Wm   = (const float*)d_in[21];
    const float* bm   = (const float*)d_in[22];
    const float* ln3s = (const float*)d_in[23];
    const float* ln3b = (const float*)d_in[24];
    float* out = (float*)d_out;

    const int n = in_sizes[0] / 512;
    const int nb1 = (n + 15) / 16;     // k_logits blocks
    const int nb2 = (n + 255) / 256;   // k_ssum blocks
    const int nb3 = (n + 63) / 64;     // k_main blocks

    const int smem_bytes = (512 * H2STRIDE + 2 * 64 * 64 + 128) * (int)sizeof(float);
    cudaFuncSetAttribute(k_main, cudaFuncAttributeMaxDynamicSharedMemorySize, smem_bytes);

    k_prep<<<1, 512>>>(Wq, bq, rk);
    k_logits<<<nb1, 512>>>(h, n);
    k_ssum<<<nb2, 512>>>(h, n);
    k_small<<<1, 512>>>(nb1, nb2, Wv, bv, lrs, lrb, l1s, l1b,
                        W1, b1, W2, b2, W3, b3, Wk, bk);
    k_main<<<nb3, 512, smem_bytes>>>(h, ln2s, ln2b, Wm, bm, ln3s, ln3b, out, n);
}

// round 3
// speedup vs baseline: 2.1208x; 1.1513x over previous
#include <cuda_runtime.h>
#include <cstdint>

#define FULL_MASK 0xFFFFFFFFu

// ------------------------- device scratch (no allocation allowed) ----------
__device__ float g_u[512 * 4];            // folded logit matrix (Wq @ rk per head)
__device__ float g_c1[4];                 // folded logit bias
__device__ float g_dpart[2048 * 4];       // per-block denominators
__device__ float g_spart[1024 * 2048];    // per-block S_r partials
__device__ float g_spart2[8 * 2048];      // stage-2 partials
__device__ float g_x1[512];
__device__ float g_x2[512];
__device__ float g_qk[1024];
__device__ float g_U[512 * 4];            // folded head-attention matrix (incl 1/sqrt(128))
__device__ float g_c[4];                  // folded head-attention bias
__device__ float g_vals[512];             // per-head value vectors (flattened)

// ------------------------- f32x2 helpers -----------------------------------
__device__ __forceinline__ unsigned long long pack2(float lo, float hi) {
    unsigned long long r;
    asm("mov.b64 %0, {%1, %2};" : "=l"(r) : "f"(lo), "f"(hi));
    return r;
}
__device__ __forceinline__ void unpack2(unsigned long long v, float& lo, float& hi) {
    asm("mov.b64 {%0, %1}, %2;" : "=f"(lo), "=f"(hi) : "l"(v));
}
__device__ __forceinline__ void fma2(unsigned long long& acc,
                                     unsigned long long a, unsigned long long b) {
    asm("fma.rn.f32x2 %0, %1, %2, %0;" : "+l"(acc) : "l"(a), "l"(b));
}
__device__ __forceinline__ float silu_fast(float x) {
    return __fdividef(x, 1.0f + __expf(-x));
}

// ------------------------- kernel: prep (fold Wq/rk -> u, c1) ---------------
__global__ void __launch_bounds__(512) k_prep(const float* __restrict__ Wq,
                                              const float* __restrict__ bq,
                                              const float* __restrict__ rk) {
    int k = threadIdx.x;
    float u[4];
#pragma unroll
    for (int r = 0; r < 4; r++) {
        float s = 0.f;
#pragma unroll
        for (int d = 0; d < 4; d++) s += Wq[k * 16 + 4 * r + d] * rk[4 * r + d];
        u[r] = s;
    }
    ((float4*)g_u)[k] = make_float4(u[0], u[1], u[2], u[3]);
    if (k < 4) {
        float s = 0.f;
#pragma unroll
        for (int d = 0; d < 4; d++) s += bq[4 * k + d] * rk[4 * k + d];
        g_c1[k] = s;
    }
}

// ------------------------- kernel: fused pass 1 -----------------------------
// 128 rows/block. Phase 1: warp-per-row logits -> e (smem) + D partial.
// Phase 2: thread-per-column S accumulation over the 128 rows (L2-hot).
__global__ void __launch_bounds__(512) k_pass1(const float* __restrict__ h, int n) {
    __shared__ float4 se[128];
    __shared__ float sD[16][4];
    const int tid = threadIdx.x, warp = tid >> 5, lane = tid & 31;
    const int base = blockIdx.x * 128;

    const float c10 = g_c1[0], c11 = g_c1[1], c12 = g_c1[2], c13 = g_c1[3];
    float d0 = 0.f, d1 = 0.f, d2 = 0.f, d3 = 0.f;

#pragma unroll
    for (int rr = 0; rr < 8; rr++) {
        const int rloc = warp * 8 + rr;
        const int row = base + rloc;
        const bool valid = (row < n);
        const float* hr = h + (size_t)row * 512;

        float l0 = 0.f, l1 = 0.f, l2 = 0.f, l3 = 0.f;
        if (valid) {
#pragma unroll
            for (int t = 0; t < 16; t++) {
                int k = lane + 32 * t;
                float hk = __ldg(hr + k);
                float4 u = __ldg((const float4*)g_u + k);
                l0 += hk * u.x; l1 += hk * u.y; l2 += hk * u.z; l3 += hk * u.w;
            }
        }
#pragma unroll
        for (int o = 16; o; o >>= 1) {
            l0 += __shfl_xor_sync(FULL_MASK, l0, o);
            l1 += __shfl_xor_sync(FULL_MASK, l1, o);
            l2 += __shfl_xor_sync(FULL_MASK, l2, o);
            l3 += __shfl_xor_sync(FULL_MASK, l3, o);
        }
        if (lane == 0) {
            float m = valid ? 1.f : 0.f;
            float e0 = m * __expf(0.5f * (l0 + c10));
            float e1 = m * __expf(0.5f * (l1 + c11));
            float e2 = m * __expf(0.5f * (l2 + c12));
            float e3 = m * __expf(0.5f * (l3 + c13));
            se[rloc] = make_float4(e0, e1, e2, e3);
            d0 += e0; d1 += e1; d2 += e2; d3 += e3;
        }
    }
    if (lane == 0) {
        sD[warp][0] = d0; sD[warp][1] = d1; sD[warp][2] = d2; sD[warp][3] = d3;
    }
    __syncthreads();
    if (warp == 0 && lane < 4) {
        float s = 0.f;
#pragma unroll
        for (int w = 0; w < 16; w++) s += sD[w][lane];
        g_dpart[blockIdx.x * 4 + lane] = s;
    }

    // Phase 2: S partials
    const int c = tid;
    int lim = n - base; if (lim > 128) lim = 128;
    unsigned long long a01 = pack2(0.f, 0.f), a23 = pack2(0.f, 0.f);
    const float* hc = h + (size_t)base * 512 + c;
#pragma unroll 4
    for (int i = 0; i < lim; i++) {
        float4 e = se[i];
        float hv = __ldg(hc + (size_t)i * 512);
        unsigned long long hd = pack2(hv, hv);
        fma2(a01, hd, pack2(e.x, e.y));
        fma2(a23, hd, pack2(e.z, e.w));
    }
    float s0, s1, s2, s3;
    unpack2(a01, s0, s1);
    unpack2(a23, s2, s3);
    float* dst = g_spart + (size_t)blockIdx.x * 2048;
    dst[0 * 512 + c] = s0;
    dst[1 * 512 + c] = s1;
    dst[2 * 512 + c] = s2;
    dst[3 * 512 + c] = s3;
}

// ------------------------- kernel: S partial reduction (grid 4x8) -----------
__global__ void __launch_bounds__(512) k_redS(int nb) {
    const int col = blockIdx.x * 512 + threadIdx.x;
    const int chunk = (nb + 7) / 8;
    int i0 = blockIdx.y * chunk;
    int i1 = i0 + chunk; if (i1 > nb) i1 = nb;
    float s = 0.f;
    const float* src = g_spart + col;
#pragma unroll 4
    for (int i = i0; i < i1; i++) s += src[(size_t)i * 2048];
    g_spart2[blockIdx.y * 2048 + col] = s;
}

// ------------------------- kernel: smallA — S/D finalize, LN chain, x1 ------
__global__ void __launch_bounds__(512) k_smallA(int nb,
        const float* __restrict__ Wv,  const float* __restrict__ bv,
        const float* __restrict__ lrs, const float* __restrict__ lrb,
        const float* __restrict__ l1s, const float* __restrict__ l1b,
        const float* __restrict__ W1,  const float* __restrict__ b1) {
    __shared__ float sS[4 * 512];
    __shared__ float sDv[4];
    __shared__ float sNum[16];
    __shared__ float sr16[16];
    const int tid = threadIdx.x, warp = tid >> 5, lane = tid & 31;

    // finalize S: 4 cols per thread
#pragma unroll
    for (int r = 0; r < 4; r++) {
        int col = r * 512 + tid;
        float s = 0.f;
#pragma unroll
        for (int j = 0; j < 8; j++) s += g_spart2[j * 2048 + col];
        sS[col] = s;
    }
    // finalize D: warps 0..3
    if (warp < 4) {
        float s = 0.f;
        for (int i = lane; i < nb; i += 32) s += g_dpart[i * 4 + warp];
#pragma unroll
        for (int o = 16; o; o >>= 1) s += __shfl_xor_sync(FULL_MASK, s, o);
        if (lane == 0) sDv[warp] = s;
    }
    __syncthreads();

    // num[i] = S_{i>>2} . Wv[:, i]
    {
        const int r = warp >> 2;
        float s = 0.f;
        for (int c = lane; c < 512; c += 32) s += sS[r * 512 + c] * Wv[c * 16 + warp];
#pragma unroll
        for (int o = 16; o; o >>= 1) s += __shfl_xor_sync(FULL_MASK, s, o);
        if (lane == 0) sNum[warp] = s;
    }
    __syncthreads();

    if (tid == 0) {
        float reg[16];
#pragma unroll
        for (int i = 0; i < 16; i++) reg[i] = sNum[i] / sDv[i >> 2] + bv[i];
#pragma unroll
        for (int pass = 0; pass < 2; pass++) {
            const float* sc = pass ? l1s : lrs;
            const float* bc = pass ? l1b : lrb;
            float m = 0.f;
            for (int i = 0; i < 16; i++) m += reg[i];
            m *= (1.f / 16.f);
            float v = 0.f;
            for (int i = 0; i < 16; i++) { float d = reg[i] - m; v += d * d; }
            v *= (1.f / 16.f);
            float inv = rsqrtf(v + 1e-6f);
            for (int i = 0; i < 16; i++) reg[i] = (reg[i] - m) * inv * sc[i] + bc[i];
        }
        for (int i = 0; i < 16; i++) sr16[i] = reg[i];
    }
    __syncthreads();

    float s = b1[tid];
#pragma unroll
    for (int i = 0; i < 16; i++) s += sr16[i] * W1[i * 512 + tid];
    g_x1[tid] = s / (1.f + expf(-s));
}

// ------------------------- kernel: smallB — x2 = silu(x1 @ W2 + b2) ---------
__global__ void __launch_bounds__(512) k_smallB(const float* __restrict__ W2,
                                                const float* __restrict__ b2) {
    __shared__ float sx1[512];
    const int tid = threadIdx.x;
    sx1[tid] = g_x1[tid];
    __syncthreads();
    float s = b2[tid];
    const float* w = W2 + tid;
#pragma unroll 16
    for (int k = 0; k < 512; k++) s += sx1[k] * __ldg(w + (size_t)k * 512);
    g_x2[tid] = s / (1.f + expf(-s));
}

// ------------------------- kernel: smallC — qk = x2 @ W3 + b3 ---------------
__global__ void __launch_bounds__(1024) k_smallC(const float* __restrict__ W3,
                                                 const float* __restrict__ b3) {
    __shared__ float sx2[512];
    const int tid = threadIdx.x;
    if (tid < 512) sx2[tid] = g_x2[tid];
    __syncthreads();
    float s = b3[tid];
    const float* w = W3 + tid;
#pragma unroll 16
    for (int k = 0; k < 512; k++) s += sx2[k] * __ldg(w + (size_t)k * 1024);
    g_qk[tid] = s;
}

// ------------------------- kernel: smallD — fold U, c, vals ------------------
__global__ void __launch_bounds__(512) k_smallD(const float* __restrict__ Wk,
                                                const float* __restrict__ bk) {
    __shared__ float sqk[1024];
    const int tid = threadIdx.x;
    sqk[tid] = g_qk[tid];
    sqk[tid + 512] = g_qk[tid + 512];
    __syncthreads();

    const float inva = rsqrtf(128.f);
    const float4* wkr = (const float4*)(Wk + (size_t)tid * 512);
    float a[4];
#pragma unroll
    for (int r = 0; r < 4; r++) {
        float s = 0.f;
#pragma unroll
        for (int d4 = 0; d4 < 32; d4++) {
            float4 w = __ldg(wkr + r * 32 + d4);
            s += w.x * sqk[r * 128 + 4 * d4 + 0];
            s += w.y * sqk[r * 128 + 4 * d4 + 1];
            s += w.z * sqk[r * 128 + 4 * d4 + 2];
            s += w.w * sqk[r * 128 + 4 * d4 + 3];
        }
        a[r] = s * inva;
    }
    ((float4*)g_U)[tid] = make_float4(a[0], a[1], a[2], a[3]);
    g_vals[tid] = sqk[512 + tid];
    if (tid < 4) {
        float s = 0.f;
        for (int d = 0; d < 128; d++) s += bk[tid * 128 + d] * sqk[tid * 128 + d];
        g_c[tid] = s * rsqrtf(128.f);
    }
}

// ------------------------- kernel: main per-row pipeline + h2@Wm ------------
#define H2STRIDE 68
__global__ void __launch_bounds__(512, 1) k_main(const float* __restrict__ h,
        const float* __restrict__ ln2s, const float* __restrict__ ln2b,
        const float* __restrict__ Wm,   const float* __restrict__ bm,
        const float* __restrict__ ln3s, const float* __restrict__ ln3b,
        float* __restrict__ out, int n) {
    extern __shared__ float sm[];
    float* h2t   = sm;                       // [512][68]
    float* red   = sm + 512 * H2STRIDE;      // [64][64] sums
    float* red2  = red + 64 * 64;            // [64][64] sumsq
    float* stats = red2 + 64 * 64;           // [64][2]

    const int tid = threadIdx.x, warp = tid >> 5, lane = tid & 31;
    const int row0 = blockIdx.x * 64;

    const float c0 = g_c[0], c1 = g_c[1], c2 = g_c[2], c3 = g_c[3];

    // ---------- Phase A ----------
#pragma unroll
    for (int rr = 0; rr < 4; rr++) {
        const int rloc = warp * 4 + rr;
        const int row = row0 + rloc;
        const bool valid = (row < n);
        const float* hr = h + (size_t)row * 512;

        float l0 = 0.f, l1 = 0.f, l2 = 0.f, l3 = 0.f;
        if (valid) {
#pragma unroll
            for (int t = 0; t < 16; t++) {
                int k = lane + 32 * t;
                float hk = __ldg(hr + k);
                float4 u = __ldg((const float4*)g_U + k);
                l0 += hk * u.x; l1 += hk * u.y; l2 += hk * u.z; l3 += hk * u.w;
            }
        }
#pragma unroll
        for (int o = 16; o; o >>= 1) {
            l0 += __shfl_xor_sync(FULL_MASK, l0, o);
            l1 += __shfl_xor_sync(FULL_MASK, l1, o);
            l2 += __shfl_xor_sync(FULL_MASK, l2, o);
            l3 += __shfl_xor_sync(FULL_MASK, l3, o);
        }
        l0 += c0; l1 += c1; l2 += c2; l3 += c3;
        float mx = fmaxf(fmaxf(l0, l1), fmaxf(l2, l3));
        float e0 = __expf(l0 - mx), e1 = __expf(l1 - mx);
        float e2 = __expf(l2 - mx), e3 = __expf(l3 - mx);
        float sinv = __fdividef(1.f, e0 + e1 + e2 + e3);
        float a0 = e0 * sinv, a1 = e1 * sinv, a2 = e2 * sinv, a3 = e3 * sinv;

        float o_[16];
        float sum = 0.f, sq = 0.f;
#pragma unroll
        for (int t = 0; t < 16; t++) {
            int k = lane + 32 * t;
            float ar = (t < 4) ? a0 : (t < 8) ? a1 : (t < 12) ? a2 : a3;
            float v = valid ? (__ldg(hr + k) + ar * g_vals[k]) : 0.f;
            o_[t] = v;
            sum += v; sq += v * v;
        }
#pragma unroll
        for (int o = 16; o; o >>= 1) {
            sum += __shfl_xor_sync(FULL_MASK, sum, o);
            sq  += __shfl_xor_sync(FULL_MASK, sq, o);
        }
        float mean = sum * (1.f / 512.f);
        float var = sq * (1.f / 512.f) - mean * mean;
        float inv = rsqrtf(var + 1e-6f);
#pragma unroll
        for (int t = 0; t < 16; t++) {
            int k = lane + 32 * t;
            h2t[k * H2STRIDE + rloc] =
                (o_[t] - mean) * inv * __ldg(ln2s + k) + __ldg(ln2b + k);
        }
    }
    __syncthreads();

    // ---------- Phase B: 8 rows x 8 cols per thread ----------
    const int cg = tid & 63;
    const int rg = tid >> 6;
    unsigned long long acc[4][8];
#pragma unroll
    for (int p = 0; p < 4; p++)
#pragma unroll
        for (int c = 0; c < 8; c++) acc[p][c] = pack2(0.f, 0.f);

    const float4* w0 = (const float4*)Wm + cg;
    const float4* w1 = w0 + 64;
    const float* hb0 = h2t + rg * 8;
#pragma unroll 4
    for (int k = 0; k < 512; k++) {
        float4 wa = __ldg(w0 + k * 128);
        float4 wb = __ldg(w1 + k * 128);
        unsigned long long wd[8];
        wd[0] = pack2(wa.x, wa.x); wd[1] = pack2(wa.y, wa.y);
        wd[2] = pack2(wa.z, wa.z); wd[3] = pack2(wa.w, wa.w);
        wd[4] = pack2(wb.x, wb.x); wd[5] = pack2(wb.y, wb.y);
        wd[6] = pack2(wb.z, wb.z); wd[7] = pack2(wb.w, wb.w);
        const float* hb = hb0 + k * H2STRIDE;
        ulonglong2 hA = *(const ulonglong2*)hb;
        ulonglong2 hB = *(const ulonglong2*)(hb + 4);
        unsigned long long hp[4] = {hA.x, hA.y, hB.x, hB.y};
#pragma unroll
        for (int p = 0; p < 4; p++)
#pragma unroll
            for (int c = 0; c < 8; c++) fma2(acc[p][c], hp[p], wd[c]);
    }

    float4 bma = __ldg((const float4*)bm + cg);
    float4 bmb = __ldg((const float4*)bm + cg + 64);
    float bmf[8] = {bma.x, bma.y, bma.z, bma.w, bmb.x, bmb.y, bmb.z, bmb.w};
    float y[8][8];
#pragma unroll
    for (int p = 0; p < 4; p++)
#pragma unroll
        for (int c = 0; c < 8; c++) {
            float lo, hi;
            unpack2(acc[p][c], lo, hi);
            y[2 * p + 0][c] = lo + bmf[c];
            y[2 * p + 1][c] = hi + bmf[c];
        }
#pragma unroll
    for (int c = 0; c < 8; c++) {
        int col = (c < 4) ? (cg * 4 + c) : (256 + cg * 4 + (c - 4));
#pragma unroll
        for (int r = 0; r < 8; r++) {
            float h2v = h2t[col * H2STRIDE + rg * 8 + r];
            y[r][c] = h2v + silu_fast(y[r][c]);
        }
    }

#pragma unroll
    for (int r = 0; r < 8; r++) {
        int rl = rg * 8 + r;
        float ps = 0.f, pss = 0.f;
#pragma unroll
        for (int c = 0; c < 8; c++) { ps += y[r][c]; pss += y[r][c] * y[r][c]; }
        red[rl * 64 + cg] = ps;
        red2[rl * 64 + cg] = pss;
    }
    __syncthreads();
#pragma unroll
    for (int rr = 0; rr < 4; rr++) {
        int rl = warp * 4 + rr;
        float s  = red[rl * 64 + lane]  + red[rl * 64 + lane + 32];
        float sq = red2[rl * 64 + lane] + red2[rl * 64 + lane + 32];
#pragma unroll
        for (int o = 16; o; o >>= 1) {
            s  += __shfl_xor_sync(FULL_MASK, s, o);
            sq += __shfl_xor_sync(FULL_MASK, sq, o);
        }
        if (lane == 0) {
            float mean = s * (1.f / 512.f);
            float var = sq * (1.f / 512.f) - mean * mean;
            stats[rl * 2 + 0] = mean;
            stats[rl * 2 + 1] = rsqrtf(var + 1e-6f);
        }
    }
    __syncthreads();

    float4 s4a = __ldg((const float4*)ln3s + cg);
    float4 b4a = __ldg((const float4*)ln3b + cg);
    float4 s4b = __ldg((const float4*)ln3s + cg + 64);
    float4 b4b = __ldg((const float4*)ln3b + cg + 64);
#pragma unroll
    for (int r = 0; r < 8; r++) {
        int rl = rg * 8 + r;
        int row = row0 + rl;
        if (row >= n) continue;
        float mean = stats[rl * 2 + 0], inv = stats[rl * 2 + 1];
        float4 o1, o2;
        o1.x = (y[r][0] - mean) * inv * s4a.x + b4a.x;
        o1.y = (y[r][1] - mean) * inv * s4a.y + b4a.y;
        o1.z = (y[r][2] - mean) * inv * s4a.z + b4a.z;
        o1.w = (y[r][3] - mean) * inv * s4a.w + b4a.w;
        o2.x = (y[r][4] - mean) * inv * s4b.x + b4b.x;
        o2.y = (y[r][5] - mean) * inv * s4b.y + b4b.y;
        o2.z = (y[r][6] - mean) * inv * s4b.z + b4b.z;
        o2.w = (y[r][7] - mean) * inv * s4b.w + b4b.w;
        *(float4*)(out + (size_t)row * 512 + cg * 4) = o1;
        *(float4*)(out + (size_t)row * 512 + 256 + cg * 4) = o2;
    }
}

// ------------------------- host launch --------------------------------------
extern "C" void kernel_launch(void* const* d_in, const int* in_sizes, int n_in,
                              void* d_out, int out_size) {
    const float* h    = (const float*)d_in[0];
    const float* rk   = (const float*)d_in[2];
    const float* Wq   = (const float*)d_in[3];
    const float* bq   = (const float*)d_in[4];
    const float* Wv   = (const float*)d_in[5];
    const float* bv   = (const float*)d_in[6];
    const float* lrs  = (const float*)d_in[7];
    const float* lrb  = (const float*)d_in[8];
    const float* l1s  = (const float*)d_in[9];
    const float* l1b  = (const float*)d_in[10];
    const float* W1   = (const float*)d_in[11];
    const float* b1   = (const float*)d_in[12];
    const float* W2   = (const float*)d_in[13];
    const float* b2   = (const float*)d_in[14];
    const float* W3   = (const float*)d_in[15];
    const float* b3   = (const float*)d_in[16];
    const float* Wk   = (const float*)d_in[17];
    const float* bk   = (const float*)d_in[18];
    const float* ln2s = (const float*)d_in[19];
    const float* ln2b = (const float*)d_in[20];
    const float* Wm   = (const float*)d_in[21];
    const float* bm   = (const float*)d_in[22];
    const float* ln3s = (const float*)d_in[23];
    const float* ln3b = (const float*)d_in[24];
    float* out = (float*)d_out;

    const int n = in_sizes[0] / 512;
    const int nb1 = (n + 127) / 128;   // k_pass1 blocks
    const int nb3 = (n + 63) / 64;     // k_main blocks

    const int smem_bytes = (512 * H2STRIDE + 2 * 64 * 64 + 128) * (int)sizeof(float);
    cudaFuncSetAttribute(k_main, cudaFuncAttributeMaxDynamicSharedMemorySize, smem_bytes);

    k_prep<<<1, 512>>>(Wq, bq, rk);
    k_pass1<<<nb1, 512>>>(h, n);
    k_redS<<<dim3(4, 8), 512>>>(nb1);
    k_smallA<<<1, 512>>>(nb1, Wv, bv, lrs, lrb, l1s, l1b, W1, b1);
    k_smallB<<<1, 512>>>(W2, b2);
    k_smallC<<<1, 1024>>>(W3, b3);
    k_smallD<<<1, 512>>>(Wk, bk);
    k_main<<<nb3, 512, smem_bytes>>>(h, ln2s, ln2b, Wm, bm, ln3s, ln3b, out, n);
}

// round 5
// speedup vs baseline: 3.1290x; 1.4754x over previous
#include <cuda_runtime.h>
#include <cuda_bf16.h>
#include <cstdint>

#define FULL_MASK 0xFFFFFFFFu

// ------------------------- device scratch ----------------------------------
__device__ float g_u[512 * 4];
__device__ float g_c1[4];
__device__ float g_dpart[2048 * 4];
__device__ float g_spart[1024 * 2048];
__device__ float g_spart2[8 * 2048];
__device__ float g_x1[512];
__device__ float g_x2[512];
__device__ float g_qk[1024];
__device__ float g_U[512 * 4];
__device__ float g_c[4];
__device__ float g_vals[512];
__device__ float g_sv[4];
__device__ float g_svv[4];
// Wm^T split hi/lo, chunk-major: [kchunk][n][kk] with kchunk = k/32, kk = k%32
__device__ __nv_bfloat16 g_WmB_hi[512 * 512];
__device__ __nv_bfloat16 g_WmB_lo[512 * 512];

// ------------------------- helpers -----------------------------------------
__device__ __forceinline__ unsigned long long pack2(float lo, float hi) {
    unsigned long long r;
    asm("mov.b64 %0, {%1, %2};" : "=l"(r) : "f"(lo), "f"(hi));
    return r;
}
__device__ __forceinline__ void unpack2(unsigned long long v, float& lo, float& hi) {
    asm("mov.b64 {%0, %1}, %2;" : "=f"(lo), "=f"(hi) : "l"(v));
}
__device__ __forceinline__ void fma2(unsigned long long& acc,
                                     unsigned long long a, unsigned long long b) {
    asm("fma.rn.f32x2 %0, %1, %2, %0;" : "+l"(acc) : "l"(a), "l"(b));
}
__device__ __forceinline__ float silu_fast(float x) {
    return __fdividef(x, 1.0f + __expf(-x));
}
__device__ __forceinline__ uint32_t smem_u32(const void* p) {
    uint32_t a;
    asm("{ .reg .u64 t; cvta.to.shared.u64 t, %1; cvt.u32.u64 %0, t; }" : "=r"(a) : "l"(p));
    return a;
}
__device__ __forceinline__ uint32_t pkbf(__nv_bfloat16 a, __nv_bfloat16 b) {
    return (uint32_t)__bfloat16_as_ushort(a) | ((uint32_t)__bfloat16_as_ushort(b) << 16);
}
__device__ __forceinline__ void cp8(uint32_t dst, const void* src) {
    asm volatile("cp.async.ca.shared.global [%0], [%1], 8;" :: "r"(dst), "l"(src));
}
__device__ __forceinline__ void mma_bf16(float& d0, float& d1, float& d2, float& d3,
                                         uint32_t a0, uint32_t a1, uint32_t a2, uint32_t a3,
                                         uint32_t b0, uint32_t b1) {
    asm volatile(
        "mma.sync.aligned.m16n8k16.row.col.f32.bf16.bf16.f32 "
        "{%0,%1,%2,%3}, {%4,%5,%6,%7}, {%8,%9}, {%0,%1,%2,%3};"
        : "+f"(d0), "+f"(d1), "+f"(d2), "+f"(d3)
        : "r"(a0), "r"(a1), "r"(a2), "r"(a3), "r"(b0), "r"(b1));
}

// ------------------------- kernel: prep (fold Wq/rk -> u, c1) ---------------
__global__ void __launch_bounds__(512) k_prep(const float* __restrict__ Wq,
                                              const float* __restrict__ bq,
                                              const float* __restrict__ rk) {
    int k = threadIdx.x;
    float u[4];
#pragma unroll
    for (int r = 0; r < 4; r++) {
        float s = 0.f;
#pragma unroll
        for (int d = 0; d < 4; d++) s += Wq[k * 16 + 4 * r + d] * rk[4 * r + d];
        u[r] = s;
    }
    ((float4*)g_u)[k] = make_float4(u[0], u[1], u[2], u[3]);
    if (k < 4) {
        float s = 0.f;
#pragma unroll
        for (int d = 0; d < 4; d++) s += bq[4 * k + d] * rk[4 * k + d];
        g_c1[k] = s;
    }
}

// ------------------------- kernel: transpose + bf16-split Wm ----------------
__global__ void __launch_bounds__(1024) k_prepWm(const float* __restrict__ Wm) {
    __shared__ float tile[32][33];
    int tx = threadIdx.x, ty = threadIdx.y;
    tile[ty][tx] = Wm[(blockIdx.y * 32 + ty) * 512 + blockIdx.x * 32 + tx];
    __syncthreads();
    // output element: k = by*32+tx, n = bx*32+ty ; chunk = by, kk = tx
    int n = blockIdx.x * 32 + ty;
    float v = tile[tx][ty];
    __nv_bfloat16 bh = __float2bfloat16(v);
    __nv_bfloat16 bl = __float2bfloat16(v - __bfloat162float(bh));
    size_t idx = ((size_t)blockIdx.y * 512 + n) * 32 + tx;
    g_WmB_hi[idx] = bh;
    g_WmB_lo[idx] = bl;
}

// ------------------------- kernel: fused pass 1 -----------------------------
__global__ void __launch_bounds__(512) k_pass1(const float* __restrict__ h, int n) {
    __shared__ float4 se[128];
    __shared__ float sD[16][4];
    const int tid = threadIdx.x, warp = tid >> 5, lane = tid & 31;
    const int base = blockIdx.x * 128;

    const float c10 = g_c1[0], c11 = g_c1[1], c12 = g_c1[2], c13 = g_c1[3];
    float d0 = 0.f, d1 = 0.f, d2 = 0.f, d3 = 0.f;

#pragma unroll
    for (int rr = 0; rr < 8; rr++) {
        const int rloc = warp * 8 + rr;
        const int row = base + rloc;
        const bool valid = (row < n);
        const float* hr = h + (size_t)row * 512;

        float l0 = 0.f, l1 = 0.f, l2 = 0.f, l3 = 0.f;
        if (valid) {
#pragma unroll
            for (int t = 0; t < 16; t++) {
                int k = lane + 32 * t;
                float hk = __ldg(hr + k);
                float4 u = __ldg((const float4*)g_u + k);
                l0 += hk * u.x; l1 += hk * u.y; l2 += hk * u.z; l3 += hk * u.w;
            }
        }
#pragma unroll
        for (int o = 16; o; o >>= 1) {
            l0 += __shfl_xor_sync(FULL_MASK, l0, o);
            l1 += __shfl_xor_sync(FULL_MASK, l1, o);
            l2 += __shfl_xor_sync(FULL_MASK, l2, o);
            l3 += __shfl_xor_sync(FULL_MASK, l3, o);
        }
        if (lane == 0) {
            float m = valid ? 1.f : 0.f;
            float e0 = m * __expf(0.5f * (l0 + c10));
            float e1 = m * __expf(0.5f * (l1 + c11));
            float e2 = m * __expf(0.5f * (l2 + c12));
            float e3 = m * __expf(0.5f * (l3 + c13));
            se[rloc] = make_float4(e0, e1, e2, e3);
            d0 += e0; d1 += e1; d2 += e2; d3 += e3;
        }
    }
    if (lane == 0) {
        sD[warp][0] = d0; sD[warp][1] = d1; sD[warp][2] = d2; sD[warp][3] = d3;
    }
    __syncthreads();
    if (warp == 0 && lane < 4) {
        float s = 0.f;
#pragma unroll
        for (int w = 0; w < 16; w++) s += sD[w][lane];
        g_dpart[blockIdx.x * 4 + lane] = s;
    }

    const int c = tid;
    int lim = n - base; if (lim > 128) lim = 128;
    unsigned long long a01 = pack2(0.f, 0.f), a23 = pack2(0.f, 0.f);
    const float* hc = h + (size_t)base * 512 + c;
#pragma unroll 4
    for (int i = 0; i < lim; i++) {
        float4 e = se[i];
        float hv = __ldg(hc + (size_t)i * 512);
        unsigned long long hd = pack2(hv, hv);
        fma2(a01, hd, pack2(e.x, e.y));
        fma2(a23, hd, pack2(e.z, e.w));
    }
    float s0, s1, s2, s3;
    unpack2(a01, s0, s1);
    unpack2(a23, s2, s3);
    float* dst = g_spart + (size_t)blockIdx.x * 2048;
    dst[0 * 512 + c] = s0;
    dst[1 * 512 + c] = s1;
    dst[2 * 512 + c] = s2;
    dst[3 * 512 + c] = s3;
}

// ------------------------- kernel: S partial reduction ----------------------
__global__ void __launch_bounds__(512) k_redS(int nb) {
    const int col = blockIdx.x * 512 + threadIdx.x;
    const int chunk = (nb + 7) / 8;
    int i0 = blockIdx.y * chunk;
    int i1 = i0 + chunk; if (i1 > nb) i1 = nb;
    float s = 0.f;
    const float* src = g_spart + col;
#pragma unroll 4
    for (int i = i0; i < i1; i++) s += src[(size_t)i * 2048];
    g_spart2[blockIdx.y * 2048 + col] = s;
}

// ------------------------- kernel: smallA -----------------------------------
__global__ void __launch_bounds__(512) k_smallA(int nb,
        const float* __restrict__ Wv,  const float* __restrict__ bv,
        const float* __restrict__ lrs, const float* __restrict__ lrb,
        const float* __restrict__ l1s, const float* __restrict__ l1b,
        const float* __restrict__ W1,  const float* __restrict__ b1) {
    __shared__ float sS[4 * 512];
    __shared__ float sDv[4];
    __shared__ float sNum[16];
    __shared__ float sr16[16];
    const int tid = threadIdx.x, warp = tid >> 5, lane = tid & 31;

#pragma unroll
    for (int r = 0; r < 4; r++) {
        int col = r * 512 + tid;
        float s = 0.f;
#pragma unroll
        for (int j = 0; j < 8; j++) s += g_spart2[j * 2048 + col];
        sS[col] = s;
    }
    if (warp < 4) {
        float s = 0.f;
        for (int i = lane; i < nb; i += 32) s += g_dpart[i * 4 + warp];
#pragma unroll
        for (int o = 16; o; o >>= 1) s += __shfl_xor_sync(FULL_MASK, s, o);
        if (lane == 0) sDv[warp] = s;
    }
    __syncthreads();

    {
        const int r = warp >> 2;
        float s = 0.f;
        for (int c = lane; c < 512; c += 32) s += sS[r * 512 + c] * Wv[c * 16 + warp];
#pragma unroll
        for (int o = 16; o; o >>= 1) s += __shfl_xor_sync(FULL_MASK, s, o);
        if (lane == 0) sNum[warp] = s;
    }
    __syncthreads();

    if (tid == 0) {
        float reg[16];
#pragma unroll
        for (int i = 0; i < 16; i++) reg[i] = sNum[i] / sDv[i >> 2] + bv[i];
#pragma unroll
        for (int pass = 0; pass < 2; pass++) {
            const float* sc = pass ? l1s : lrs;
            const float* bc = pass ? l1b : lrb;
            float m = 0.f;
            for (int i = 0; i < 16; i++) m += reg[i];
            m *= (1.f / 16.f);
            float v = 0.f;
            for (int i = 0; i < 16; i++) { float d = reg[i] - m; v += d * d; }
            v *= (1.f / 16.f);
            float inv = rsqrtf(v + 1e-6f);
            for (int i = 0; i < 16; i++) reg[i] = (reg[i] - m) * inv * sc[i] + bc[i];
        }
        for (int i = 0; i < 16; i++) sr16[i] = reg[i];
    }
    __syncthreads();

    float s = b1[tid];
#pragma unroll
    for (int i = 0; i < 16; i++) s += sr16[i] * W1[i * 512 + tid];
    g_x1[tid] = s / (1.f + expf(-s));
}

// ------------------------- kernel: smallB -----------------------------------
__global__ void __launch_bounds__(512) k_smallB(const float* __restrict__ W2,
                                                const float* __restrict__ b2) {
    __shared__ float sx1[512];
    const int tid = threadIdx.x;
    sx1[tid] = g_x1[tid];
    __syncthreads();
    float s = b2[tid];
    const float* w = W2 + tid;
#pragma unroll 16
    for (int k = 0; k < 512; k++) s += sx1[k] * __ldg(w + (size_t)k * 512);
    g_x2[tid] = s / (1.f + expf(-s));
}

// ------------------------- kernel: smallC -----------------------------------
__global__ void __launch_bounds__(1024) k_smallC(const float* __restrict__ W3,
                                                 const float* __restrict__ b3) {
    __shared__ float sx2[512];
    const int tid = threadIdx.x;
    if (tid < 512) sx2[tid] = g_x2[tid];
    __syncthreads();
    float s = b3[tid];
    const float* w = W3 + tid;
#pragma unroll 16
    for (int k = 0; k < 512; k++) s += sx2[k] * __ldg(w + (size_t)k * 1024);
    g_qk[tid] = s;
}

// ------------------------- kernel: smallD -----------------------------------
__global__ void __launch_bounds__(512) k_smallD(const float* __restrict__ Wk,
                                                const float* __restrict__ bk) {
    __shared__ float sqk[1024];
    const int tid = threadIdx.x;
    sqk[tid] = g_qk[tid];
    sqk[tid + 512] = g_qk[tid + 512];
    __syncthreads();

    const float inva = rsqrtf(128.f);
    const float4* wkr = (const float4*)(Wk + (size_t)tid * 512);
    float a[4];
#pragma unroll
    for (int r = 0; r < 4; r++) {
        float s = 0.f;
#pragma unroll
        for (int d4 = 0; d4 < 32; d4++) {
            float4 w = __ldg(wkr + r * 32 + d4);
            s += w.x * sqk[r * 128 + 4 * d4 + 0];
            s += w.y * sqk[r * 128 + 4 * d4 + 1];
            s += w.z * sqk[r * 128 + 4 * d4 + 2];
            s += w.w * sqk[r * 128 + 4 * d4 + 3];
        }
        a[r] = s * inva;
    }
    ((float4*)g_U)[tid] = make_float4(a[0], a[1], a[2], a[3]);
    g_vals[tid] = sqk[512 + tid];
    if (tid < 4) {
        float s = 0.f;
        for (int d = 0; d < 128; d++) s += bk[tid * 128 + d] * sqk[tid * 128 + d];
        g_c[tid] = s * rsqrtf(128.f);
        float sv = 0.f, svv = 0.f;
        for (int d = 0; d < 128; d++) {
            float v = sqk[512 + tid * 128 + d];
            sv += v; svv += v * v;
        }
        g_sv[tid] = sv;
        g_svv[tid] = svv;
    }
}

// ------------------------- kernel: main (HMMA bf16x3) -----------------------
// Block: 64 rows x 512 cols, 512 threads (16 warps, warp tile 32x64).
// K chunked at 32, double buffered; B via cp.async, A built in-kernel with LN2.
#define BSTRIDE 80
#define B_BUF_STRIDE 81920
#define B_LO_OFF 40960
#define OFF_A 163840
#define A_BUF_STRIDE 10240
#define A_LO_OFF 5120
#define OFF_SA 184320
#define OFF_MEAN 185344
#define OFF_INV 185600
#define SMEM_DYN 185856

__device__ __forceinline__ void loadB_async(uint32_t base32, int buf, int kc, int tid) {
    const __nv_bfloat16* sH = g_WmB_hi + (size_t)kc * 16384;
    const __nv_bfloat16* sL = g_WmB_lo + (size_t)kc * 16384;
    uint32_t bh = base32 + buf * B_BUF_STRIDE;
    uint32_t bl = bh + B_LO_OFF;
#pragma unroll
    for (int j = 0; j < 8; j++) {
        int f = j * 512 + tid;
        uint32_t doff = (uint32_t)((f >> 3) * BSTRIDE + (f & 7) * 8);
        cp8(bh + doff, sH + f * 4);
        cp8(bl + doff, sL + f * 4);
    }
}

__device__ __forceinline__ void build_a_sts(char* sb, int buf, int kc, int arow, int kq,
        float4 hv, bool valid, const float* sa, const float* smean, const float* sinv,
        const float* __restrict__ ln2s, const float* __restrict__ ln2b) {
    const int kg = kc * 32 + kq * 4;
    const float ah = sa[arow * 4 + (kc >> 2)];
    const float mean = smean[arow], inv = sinv[arow];
    float4 vv = __ldg((const float4*)(g_vals + kg));
    float4 s4 = __ldg((const float4*)(ln2s + kg));
    float4 b4 = __ldg((const float4*)(ln2b + kg));
    float hvv[4] = {hv.x, hv.y, hv.z, hv.w};
    float vvv[4] = {vv.x, vv.y, vv.z, vv.w};
    float sss[4] = {s4.x, s4.y, s4.z, s4.w};
    float bbb[4] = {b4.x, b4.y, b4.z, b4.w};
    uint32_t hi[2], lo[2];
#pragma unroll
    for (int p = 0; p < 2; p++) {
        __nv_bfloat16 bh[2], bl[2];
#pragma unroll
        for (int e = 0; e < 2; e++) {
            int i = 2 * p + e;
            float x = valid ? ((hvv[i] + ah * vvv[i] - mean) * inv * sss[i] + bbb[i]) : 0.f;
            bh[e] = __float2bfloat16(x);
            bl[e] = __float2bfloat16(x - __bfloat162float(bh[e]));
        }
        hi[p] = pkbf(bh[0], bh[1]);
        lo[p] = pkbf(bl[0], bl[1]);
    }
    char* dst = sb + OFF_A + buf * A_BUF_STRIDE + arow * BSTRIDE + kq * 8;
    *(uint2*)dst = make_uint2(hi[0], hi[1]);
    *(uint2*)(dst + A_LO_OFF) = make_uint2(lo[0], lo[1]);
}

__global__ void __launch_bounds__(512, 1) k_main_mma(const float* __restrict__ h,
        const float* __restrict__ ln2s, const float* __restrict__ ln2b,
        const float* __restrict__ bm,
        const float* __restrict__ ln3s, const float* __restrict__ ln3b,
        float* __restrict__ out, int n) {
    extern __shared__ char sb[];
    const uint32_t base32 = smem_u32(sb);
    float* sa    = (float*)(sb + OFF_SA);
    float* smean = (float*)(sb + OFF_MEAN);
    float* sinv  = (float*)(sb + OFF_INV);
    float* sd    = (float*)sb;

    const int tid = threadIdx.x, warp = tid >> 5, lane = tid & 31;
    const int row0 = blockIdx.x * 64;

    // ---------- Phase A: per-row softmax + closed-form LN2 stats ------------
    {
        const float c0 = g_c[0], c1 = g_c[1], c2 = g_c[2], c3 = g_c[3];
        const float sv0 = g_sv[0], sv1 = g_sv[1], sv2 = g_sv[2], sv3 = g_sv[3];
        const float w0 = g_svv[0], w1 = g_svv[1], w2 = g_svv[2], w3 = g_svv[3];
#pragma unroll
        for (int rr = 0; rr < 4; rr++) {
            const int rloc = warp * 4 + rr;
            const int row = row0 + rloc;
            const bool valid = (row < n);
            const float* hr = h + (size_t)row * 512;
            float l0 = 0.f, l1 = 0.f, l2 = 0.f, l3 = 0.f;
            float hv0 = 0.f, hv1 = 0.f, hv2 = 0.f, hv3 = 0.f;
            float sh = 0.f, sq = 0.f;
            if (valid) {
#pragma unroll
                for (int t = 0; t < 16; t++) {
                    int k = lane + 32 * t;
                    float hk = __ldg(hr + k);
                    float4 u = __ldg((const float4*)g_U + k);
                    float vk = __ldg(g_vals + k);
                    l0 += hk * u.x; l1 += hk * u.y; l2 += hk * u.z; l3 += hk * u.w;
                    float p = hk * vk;
                    if (t < 4) hv0 += p; else if (t < 8) hv1 += p;
                    else if (t < 12) hv2 += p; else hv3 += p;
                    sh += hk; sq += hk * hk;
                }
            }
#pragma unroll
            for (int o = 16; o; o >>= 1) {
                l0 += __shfl_xor_sync(FULL_MASK, l0, o);
                l1 += __shfl_xor_sync(FULL_MASK, l1, o);
                l2 += __shfl_xor_sync(FULL_MASK, l2, o);
                l3 += __shfl_xor_sync(FULL_MASK, l3, o);
                hv0 += __shfl_xor_sync(FULL_MASK, hv0, o);
                hv1 += __shfl_xor_sync(FULL_MASK, hv1, o);
                hv2 += __shfl_xor_sync(FULL_MASK, hv2, o);
                hv3 += __shfl_xor_sync(FULL_MASK, hv3, o);
                sh += __shfl_xor_sync(FULL_MASK, sh, o);
                sq += __shfl_xor_sync(FULL_MASK, sq, o);
            }
            if (lane == 0) {
                if (valid) {
                    l0 += c0; l1 += c1; l2 += c2; l3 += c3;
                    float mx = fmaxf(fmaxf(l0, l1), fmaxf(l2, l3));
                    float e0 = __expf(l0 - mx), e1 = __expf(l1 - mx);
                    float e2 = __expf(l2 - mx), e3 = __expf(l3 - mx);
                    float si = __fdividef(1.f, e0 + e1 + e2 + e3);
                    float a0 = e0 * si, a1 = e1 * si, a2 = e2 * si, a3 = e3 * si;
                    float sum = sh + a0 * sv0 + a1 * sv1 + a2 * sv2 + a3 * sv3;
                    float ssq = sq + 2.f * (a0 * hv0 + a1 * hv1 + a2 * hv2 + a3 * hv3)
                              + a0 * a0 * w0 + a1 * a1 * w1 + a2 * a2 * w2 + a3 * a3 * w3;
                    float mean = sum * (1.f / 512.f);
                    float var = ssq * (1.f / 512.f) - mean * mean;
                    sa[rloc * 4 + 0] = a0; sa[rloc * 4 + 1] = a1;
                    sa[rloc * 4 + 2] = a2; sa[rloc * 4 + 3] = a3;
                    smean[rloc] = mean;
                    sinv[rloc] = rsqrtf(var + 1e-6f);
                } else {
                    sa[rloc * 4 + 0] = 0.f; sa[rloc * 4 + 1] = 0.f;
                    sa[rloc * 4 + 2] = 0.f; sa[rloc * 4 + 3] = 0.f;
                    smean[rloc] = 0.f; sinv[rloc] = 0.f;
                }
            }
        }
    }
    __syncthreads();

    // ---------- GEMM pipeline ------------------------------------------------
    const int arow = tid >> 3, kq = tid & 7;
    const bool avalid = (row0 + arow < n);
    const int rowg = warp >> 3, colg = warp & 7;
    const int g = lane >> 2, tig = lane & 3;

    float d0[8][4], d1[8][4];
#pragma unroll
    for (int nt = 0; nt < 8; nt++)
#pragma unroll
        for (int e = 0; e < 4; e++) { d0[nt][e] = 0.f; d1[nt][e] = 0.f; }

    // prologue: chunk 0
    {
        loadB_async(base32, 0, 0, tid);
        asm volatile("cp.async.commit_group;" ::: "memory");
        float4 hv = make_float4(0.f, 0.f, 0.f, 0.f);
        if (avalid) hv = __ldg((const float4*)(h + (size_t)(row0 + arow) * 512 + kq * 4));
        build_a_sts(sb, 0, 0, arow, kq, hv, avalid, sa, smean, sinv, ln2s, ln2b);
        asm volatile("cp.async.wait_group 0;" ::: "memory");
        __syncthreads();
    }

    for (int kc = 0; kc < 16; kc++) {
        const int buf = kc & 1, nxt = buf ^ 1;
        float4 hv = make_float4(0.f, 0.f, 0.f, 0.f);
        if (kc < 15) {
            loadB_async(base32, nxt, kc + 1, tid);
            asm volatile("cp.async.commit_group;" ::: "memory");
            if (avalid)
                hv = __ldg((const float4*)(h + (size_t)(row0 + arow) * 512 + (kc + 1) * 32 + kq * 4));
        }

        // MMA on current buffer
        {
            const char* Ah = sb + OFF_A + buf * A_BUF_STRIDE;
            const char* Al = Ah + A_LO_OFF;
            const char* Bh = sb + buf * B_BUF_STRIDE;
            const char* Bl = Bh + B_LO_OFF;
            const int r00 = rowg * 32 + g;
            const int nb0 = colg * 64 + g;
#pragma unroll
            for (int ks = 0; ks < 2; ks++) {
                const int kb = ks * 32 + tig * 4;
                uint32_t ah[8], al[8];
#pragma unroll
                for (int rf = 0; rf < 2; rf++) {
                    const char* base = Ah + (r00 + rf * 16) * BSTRIDE + kb;
                    ah[rf * 4 + 0] = *(const uint32_t*)(base);
                    ah[rf * 4 + 1] = *(const uint32_t*)(base + 8 * BSTRIDE);
                    ah[rf * 4 + 2] = *(const uint32_t*)(base + 16);
                    ah[rf * 4 + 3] = *(const uint32_t*)(base + 8 * BSTRIDE + 16);
                    const char* basl = Al + (r00 + rf * 16) * BSTRIDE + kb;
                    al[rf * 4 + 0] = *(const uint32_t*)(basl);
                    al[rf * 4 + 1] = *(const uint32_t*)(basl + 8 * BSTRIDE);
                    al[rf * 4 + 2] = *(const uint32_t*)(basl + 16);
                    al[rf * 4 + 3] = *(const uint32_t*)(basl + 8 * BSTRIDE + 16);
                }
#pragma unroll
                for (int nt = 0; nt < 8; nt++) {
                    const char* bb = Bh + (nb0 + nt * 8) * BSTRIDE + kb;
                    uint32_t bh0 = *(const uint32_t*)(bb);
                    uint32_t bh1 = *(const uint32_t*)(bb + 16);
                    const char* bbl = Bl + (nb0 + nt * 8) * BSTRIDE + kb;
                    uint32_t bl0 = *(const uint32_t*)(bbl);
                    uint32_t bl1 = *(const uint32_t*)(bbl + 16);
                    mma_bf16(d0[nt][0], d0[nt][1], d0[nt][2], d0[nt][3],
                             ah[0], ah[1], ah[2], ah[3], bh0, bh1);
                    mma_bf16(d0[nt][0], d0[nt][1], d0[nt][2], d0[nt][3],
                             al[0], al[1], al[2], al[3], bh0, bh1);
                    mma_bf16(d0[nt][0], d0[nt][1], d0[nt][2], d0[nt][3],
                             ah[0], ah[1], ah[2], ah[3], bl0, bl1);
                    mma_bf16(d1[nt][0], d1[nt][1], d1[nt][2], d1[nt][3],
                             ah[4], ah[5], ah[6], ah[7], bh0, bh1);
                    mma_bf16(d1[nt][0], d1[nt][1], d1[nt][2], d1[nt][3],
                             al[4], al[5], al[6], al[7], bh0, bh1);
                    mma_bf16(d1[nt][0], d1[nt][1], d1[nt][2], d1[nt][3],
                             ah[4], ah[5], ah[6], ah[7], bl0, bl1);
                }
            }
        }

        if (kc < 15)
            build_a_sts(sb, nxt, kc + 1, arow, kq, hv, avalid, sa, smean, sinv, ln2s, ln2b);
        asm volatile("cp.async.wait_group 0;" ::: "memory");
        __syncthreads();
    }

    // ---------- stage D to smem ---------------------------------------------
#pragma unroll
    for (int nt = 0; nt < 8; nt++) {
        const int c0 = colg * 64 + nt * 8 + 2 * tig;
        const int ra = rowg * 32 + g;
        *(float2*)(sd + (size_t)ra * 520 + c0)        = make_float2(d0[nt][0], d0[nt][1]);
        *(float2*)(sd + (size_t)(ra + 8) * 520 + c0)  = make_float2(d0[nt][2], d0[nt][3]);
        *(float2*)(sd + (size_t)(ra + 16) * 520 + c0) = make_float2(d1[nt][0], d1[nt][1]);
        *(float2*)(sd + (size_t)(ra + 24) * 520 + c0) = make_float2(d1[nt][2], d1[nt][3]);
    }
    __syncthreads();

    // ---------- epilogue: y = h2n + silu(D + bm), LN3, write -----------------
    {
        const int prow = tid >> 3, cs = tid & 7;
        const int row = row0 + prow;
        const bool pv = (row < n);
        const float mean2 = smean[prow], inv2 = sinv[prow];
        float ar[4] = {sa[prow * 4 + 0], sa[prow * 4 + 1],
                       sa[prow * 4 + 2], sa[prow * 4 + 3]};
        float y[16][4];
        float s = 0.f, sq = 0.f;
        if (pv) {
            const float* hr = h + (size_t)row * 512;
#pragma unroll
            for (int j = 0; j < 16; j++) {
                const int c = cs * 4 + 32 * j;
                const float ah = ar[c >> 7];
                float4 hvv = __ldg((const float4*)(hr + c));
                float4 dv = *(const float4*)(sd + (size_t)prow * 520 + c);
                float4 vv = __ldg((const float4*)(g_vals + c));
                float4 s2 = __ldg((const float4*)(ln2s + c));
                float4 b2 = __ldg((const float4*)(ln2b + c));
                float4 bmv = __ldg((const float4*)(bm + c));
                float hx[4] = {hvv.x, hvv.y, hvv.z, hvv.w};
                float dx[4] = {dv.x, dv.y, dv.z, dv.w};
                float vx[4] = {vv.x, vv.y, vv.z, vv.w};
                float sx[4] = {s2.x, s2.y, s2.z, s2.w};
                float bx[4] = {b2.x, b2.y, b2.z, b2.w};
                float mx[4] = {bmv.x, bmv.y, bmv.z, bmv.w};
#pragma unroll
                for (int e = 0; e < 4; e++) {
                    float h2n = (hx[e] + ah * vx[e] - mean2) * inv2 * sx[e] + bx[e];
                    float yv = h2n + silu_fast(dx[e] + mx[e]);
                    y[j][e] = yv;
                    s += yv; sq += yv * yv;
                }
            }
        }
        // reduce across 8 lanes of the same row (consecutive lanes, xor 1,2,4)
        s  += __shfl_xor_sync(FULL_MASK, s, 1);
        s  += __shfl_xor_sync(FULL_MASK, s, 2);
        s  += __shfl_xor_sync(FULL_MASK, s, 4);
        sq += __shfl_xor_sync(FULL_MASK, sq, 1);
        sq += __shfl_xor_sync(FULL_MASK, sq, 2);
        sq += __shfl_xor_sync(FULL_MASK, sq, 4);
        if (pv) {
            float mean = s * (1.f / 512.f);
            float var = sq * (1.f / 512.f) - mean * mean;
            float inv = rsqrtf(var + 1e-6f);
            float* orow = out + (size_t)row * 512;
#pragma unroll
            for (int j = 0; j < 16; j++) {
                const int c = cs * 4 + 32 * j;
                float4 sc = __ldg((const float4*)(ln3s + c));
                float4 bc = __ldg((const float4*)(ln3b + c));
                float4 o;
                o.x = (y[j][0] - mean) * inv * sc.x + bc.x;
                o.y = (y[j][1] - mean) * inv * sc.y + bc.y;
                o.z = (y[j][2] - mean) * inv * sc.z + bc.z;
                o.w = (y[j][3] - mean) * inv * sc.w + bc.w;
                *(float4*)(orow + c) = o;
            }
        }
    }
}

// ------------------------- host launch --------------------------------------
extern "C" void kernel_launch(void* const* d_in, const int* in_sizes, int n_in,
                              void* d_out, int out_size) {
    const float* h    = (const float*)d_in[0];
    const float* rk   = (const float*)d_in[2];
    const float* Wq   = (const float*)d_in[3];
    const float* bq   = (const float*)d_in[4];
    const float* Wv   = (const float*)d_in[5];
    const float* bv   = (const float*)d_in[6];
    const float* lrs  = (const float*)d_in[7];
    const float* lrb  = (const float*)d_in[8];
    const float* l1s  = (const float*)d_in[9];
    const float* l1b  = (const float*)d_in[10];
    const float* W1   = (const float*)d_in[11];
    const float* b1   = (const float*)d_in[12];
    const float* W2   = (const float*)d_in[13];
    const float* b2   = (const float*)d_in[14];
    const float* W3   = (const float*)d_in[15];
    const float* b3   = (const float*)d_in[16];
    const float* Wk   = (const float*)d_in[17];
    const float* bk   = (const float*)d_in[18];
    const float* ln2s = (const float*)d_in[19];
    const float* ln2b = (const float*)d_in[20];
    const float* Wm   = (const float*)d_in[21];
    const float* bm   = (const float*)d_in[22];
    const float* ln3s = (const float*)d_in[23];
    const float* ln3b = (const float*)d_in[24];
    float* out = (float*)d_out;

    const int n = in_sizes[0] / 512;
    const int nb1 = (n + 127) / 128;
    const int nbm = (n + 63) / 64;

    cudaFuncSetAttribute(k_main_mma, cudaFuncAttributeMaxDynamicSharedMemorySize, SMEM_DYN);

    k_prep<<<1, 512>>>(Wq, bq, rk);
    k_prepWm<<<dim3(16, 16), dim3(32, 32)>>>(Wm);
    k_pass1<<<nb1, 512>>>(h, n);
    k_redS<<<dim3(4, 8), 512>>>(nb1);
    k_smallA<<<1, 512>>>(nb1, Wv, bv, lrs, lrb, l1s, l1b, W1, b1);
    k_smallB<<<1, 512>>>(W2, b2);
    k_smallC<<<1, 1024>>>(W3, b3);
    k_smallD<<<1, 512>>>(Wk, bk);
    k_main_mma<<<nbm, 512, SMEM_DYN>>>(h, ln2s, ln2b, bm, ln3s, ln3b, out, n);
}